// round 15
// baseline (speedup 1.0000x reference)
#include <cuda_runtime.h>
#include <cuda_fp16.h>
#include <math.h>
#include <stdint.h>

#define Bb 128
#define Uu 16
#define Dd 256
#define Nn 1024
#define Oo 256

__device__ float g_lr[Bb * Uu];

// fp16 tile images
// g_At [u][40kt][128m x 40h]      : state-GEMM A tiles (X | sr*state)
// g_NSt[u][2mt][32kt][64m x 40h]  : out-GEMM A tiles (fp16 new_state)
__device__ uint4 g_At[409600];
__device__ uint4 g_NSt[327680];

// ---------------------------------------------------------------------------
// helpers
// ---------------------------------------------------------------------------
__device__ __forceinline__ uint32_t sptr(const void* p) {
    return (uint32_t)__cvta_generic_to_shared(p);
}
__device__ __forceinline__ void ldmA(uint32_t* r, uint32_t addr) {
    asm volatile("ldmatrix.sync.aligned.m8n8.x4.shared.b16 {%0,%1,%2,%3}, [%4];"
                 : "=r"(r[0]), "=r"(r[1]), "=r"(r[2]), "=r"(r[3]) : "r"(addr));
}
__device__ __forceinline__ void ldmBT(uint32_t* r, uint32_t addr) {
    asm volatile("ldmatrix.sync.aligned.m8n8.x4.trans.shared.b16 {%0,%1,%2,%3}, [%4];"
                 : "=r"(r[0]), "=r"(r[1]), "=r"(r[2]), "=r"(r[3]) : "r"(addr));
}
__device__ __forceinline__ void mma16816(float* c, const uint32_t* a, const uint32_t* b) {
    asm volatile(
        "mma.sync.aligned.m16n8k16.row.col.f32.f16.f16.f32 "
        "{%0,%1,%2,%3},{%4,%5,%6,%7},{%8,%9},{%0,%1,%2,%3};"
        : "+f"(c[0]), "+f"(c[1]), "+f"(c[2]), "+f"(c[3])
        : "r"(a[0]), "r"(a[1]), "r"(a[2]), "r"(a[3]), "r"(b[0]), "r"(b[1]));
}
__device__ __forceinline__ uint32_t h2pack(float x, float y) {
    __half2 h = __floats2half2_rn(x, y);
    return *(uint32_t*)&h;
}
__device__ __forceinline__ uint4 pack8(float4 a, float4 b) {
    return make_uint4(h2pack(a.x, a.y), h2pack(a.z, a.w),
                      h2pack(b.x, b.y), h2pack(b.z, b.w));
}

#define CPA16(dst, src) \
    asm volatile("cp.async.cg.shared.global [%0], [%1], 16;" :: "r"(dst), "l"(src))
#define CPCOMMIT() asm volatile("cp.async.commit_group;" ::: "memory")
#define CPWAIT1()  asm volatile("cp.async.wait_group 1;" ::: "memory")
#define CPWAIT0()  asm volatile("cp.async.wait_group 0;" ::: "memory")

// ---------------------------------------------------------------------------
// Kernel 0: prep (A tiles only) + lr softmax folded in.
// grid.x = 256 convert blocks + 128 lr blocks. 256 threads.
// ---------------------------------------------------------------------------
__global__ __launch_bounds__(256) void prep_kernel(
    const float* __restrict__ X,
    const float* __restrict__ state,
    const float* __restrict__ sr,
    const float* __restrict__ alr,
    const float* __restrict__ temp)
{
    const int t = threadIdx.x;

    if (blockIdx.x >= 256) {
        // ---- lr for batch b
        __shared__ float logits[Uu];
        const int b = blockIdx.x - 256;
        const int u = t >> 4;
        const int l16 = t & 15;
        const float* xp = X + (b * Uu + u) * Dd;
        const float* ap = alr + u * Dd;
        float s = 0.f;
        #pragma unroll
        for (int d = l16; d < Dd; d += 16) s += xp[d] * ap[d];
        #pragma unroll
        for (int off = 1; off < 16; off <<= 1) s += __shfl_xor_sync(0xffffffffu, s, off);
        if (l16 == 0) logits[u] = s / temp[0];
        __syncthreads();
        if (t == 0) {
            float m = -INFINITY;
            #pragma unroll
            for (int i = 0; i < Uu; i++) m = fmaxf(m, logits[i]);
            float e[Uu], denom = 0.f;
            #pragma unroll
            for (int i = 0; i < Uu; i++) { e[i] = __expf(logits[i] - m); denom += e[i]; }
            float inv = 1.f / denom;
            #pragma unroll
            for (int i = 0; i < Uu; i++) g_lr[b * Uu + i] = e[i] * inv;
        }
        return;
    }

    const int tid = blockIdx.x * 256 + t;
    const int nth = 256 * 256;
    __half* At = (__half*)g_At;

    // A-X: u,b,k8(32) -> 65536
    for (int i = tid; i < 65536; i += nth) {
        int u = i >> 12, r = i & 4095, b = r >> 5, k8 = r & 31;
        const float4* s = (const float4*)X + ((size_t)(b * Uu + u) * 64 + k8 * 2);
        float4 v0 = s[0], v1 = s[1];
        int k = k8 * 8, kt = k >> 5;
        *(uint4*)(At + ((size_t)(u * 40 + kt)) * 5120 + b * 40 + (k & 31)) = pack8(v0, v1);
    }
    // A-state: u,b,k8(128) -> 262144 (fold sr)
    for (int i = tid; i < 262144; i += nth) {
        int u = i >> 14, r = i & 16383, b = r >> 7, k8 = r & 127;
        float srv = __ldg(sr + u);
        const float4* s = (const float4*)state + ((size_t)(b * Uu + u) * 256 + k8 * 2);
        float4 v0 = s[0], v1 = s[1];
        v0.x *= srv; v0.y *= srv; v0.z *= srv; v0.w *= srv;
        v1.x *= srv; v1.y *= srv; v1.z *= srv; v1.w *= srv;
        int k = 256 + k8 * 8, kt = k >> 5;
        *(uint4*)(At + ((size_t)(u * 40 + kt)) * 5120 + b * 40 + (k & 31)) = pack8(v0, v1);
    }
}

// ---------------------------------------------------------------------------
// Kernel 2: state GEMM. A tiles fp16 (g_At) + B fp32 direct (Win/W), inline
// convert. BM=128, BN=64, BK=32, 40 kts, 3-stage cp.async.
// 256 thr = 8 warps (2m x 4n); warp 64m x 16n. grid = (16 nt, 16 u) = 256 blk.
// smem: A 3x10240 | F32 3x8704 | F16 2x4608 = 66048 B -> 2 blocks/SM.
// ---------------------------------------------------------------------------
#define SA_OFF   0
#define SF32_OFF 30720
#define SF16_OFF 56832
#define ST_SMEM  66048

__global__ __launch_bounds__(256) void state_kernel(
    const float* __restrict__ state,
    const float* __restrict__ bias,
    const float* __restrict__ W,
    const float* __restrict__ Win,
    float* __restrict__ out_state)
{
    extern __shared__ __align__(16) char smem[];
    const int t = threadIdx.x;
    const int lane = t & 31;
    const int w = t >> 5;
    const int mw = (w & 1) * 64;
    const int nw = (w >> 1) * 16;
    const int u = blockIdx.y;
    const int nt = blockIdx.x;
    const int n0 = nt * 64;

    const __half* gA = (const __half*)g_At + (size_t)(u * 40) * 5120;

    auto ISSUE = [&](int kt) {
        int s = kt % 3;
        // A fp16 tile: 640 x 16B
        char* Asm = smem + SA_OFF + s * 10240;
        const char* gAsrc = (const char*)(gA + (size_t)kt * 5120);
        #pragma unroll
        for (int i = 0; i < 3; i++) {
            int q = t + i * 256;
            if (q < 640) CPA16(sptr(Asm + q * 16), gAsrc + q * 16);
        }
        // B fp32 tile: 32 k-rows x 256B = 512 x 16B, row stride 272B
        char* Bf = smem + SF32_OFF + s * 8704;
        int kg0 = kt * 32;
        const float* bbase = (kg0 < Dd)
            ? (Win + ((size_t)u * Dd + kg0) * Nn + n0)
            : (W + ((size_t)u * Nn + (kg0 - Dd)) * Nn + n0);
        #pragma unroll
        for (int i = 0; i < 2; i++) {
            int q = t + i * 256;
            int r = q >> 4, c16 = q & 15;
            CPA16(sptr(Bf + r * 272 + c16 * 16), (const char*)(bbase + (size_t)r * Nn + c16 * 4));
        }
        CPCOMMIT();
    };

    auto CONVERT = [&](int kt) {
        const char* Bf = smem + SF32_OFF + (kt % 3) * 8704;
        __half* Bh = (__half*)(smem + SF16_OFF + (kt & 1) * 4608);
        #pragma unroll
        for (int i = 0; i < 2; i++) {
            int q = t + i * 256;
            int r = q >> 4, c16 = q & 15;
            float4 v = *(const float4*)(Bf + r * 272 + c16 * 16);
            uint2 p = make_uint2(h2pack(v.x, v.y), h2pack(v.z, v.w));
            *(uint2*)(Bh + r * 72 + c16 * 4) = p;
        }
    };

    float acc[4][2][4];
    #pragma unroll
    for (int i = 0; i < 4; i++)
        #pragma unroll
        for (int j = 0; j < 2; j++)
            #pragma unroll
            for (int c = 0; c < 4; c++) acc[i][j][c] = 0.f;

    ISSUE(0); ISSUE(1);

    for (int kt = 0; kt < 40; kt++) {
        // wait_group 1 does not guarantee group kt complete when it is the
        // only outstanding group (tail) — drain fully there.
        if (kt + 1 < 40) { CPWAIT1(); } else { CPWAIT0(); }
        __syncthreads();
        CONVERT(kt);
        __syncthreads();
        if (kt + 2 < 40) ISSUE(kt + 2);

        const __half* As = (const __half*)(smem + SA_OFF + (kt % 3) * 10240);
        const __half* Bs = (const __half*)(smem + SF16_OFF + (kt & 1) * 4608);
        #pragma unroll
        for (int ks = 0; ks < 2; ks++) {
            const int kc = ks * 16;
            uint32_t af[4][4];
            {
                int i = lane & 7, grp = lane >> 3;
                int mrow = (grp & 1) * 8 + i;
                int kcol = kc + (grp >> 1) * 8;
                #pragma unroll
                for (int mt = 0; mt < 4; mt++)
                    ldmA(af[mt], sptr(As + (mw + mt * 16 + mrow) * 40 + kcol));
            }
            uint32_t bf[2][2];
            {
                int i = lane & 7, grp = lane >> 3;
                int krow = kc + (grp & 1) * 8 + i;
                int ncol = nw + (grp >> 1) * 8;
                uint32_t r[4];
                ldmBT(r, sptr(Bs + krow * 72 + ncol));
                bf[0][0] = r[0]; bf[0][1] = r[1];
                bf[1][0] = r[2]; bf[1][1] = r[3];
            }
            #pragma unroll
            for (int mt = 0; mt < 4; mt++)
                #pragma unroll
                for (int ntt = 0; ntt < 2; ntt++)
                    mma16816(acc[mt][ntt], af[mt], bf[ntt]);
        }
    }

    // epilogue: bias + tanh + leaky mix; also write fp16 tile image for out GEMM
    __half* NSt = (__half*)g_NSt;
    #pragma unroll
    for (int mt = 0; mt < 4; mt++) {
        #pragma unroll
        for (int half = 0; half < 2; half++) {
            int m = mw + mt * 16 + half * 8 + (lane >> 2);
            float lrv = g_lr[m * Uu + u];
            #pragma unroll
            for (int ntt = 0; ntt < 2; ntt++) {
                int n = n0 + nw + ntt * 8 + (lane & 3) * 2;
                float c0 = acc[mt][ntt][half * 2 + 0];
                float c1 = acc[mt][ntt][half * 2 + 1];
                size_t ro = ((size_t)m * Uu + u) * Nn + n;
                float2 so = *(const float2*)(state + ro);
                float2 bi = *(const float2*)(bias + (size_t)u * Nn + n);
                float2 res;
                res.x = so.x + lrv * (tanhf(c0 + bi.x) - so.x);
                res.y = so.y + lrv * (tanhf(c1 + bi.y) - so.y);
                *(float2*)(out_state + ro) = res;
                __half2 h = __floats2half2_rn(res.x, res.y);
                *(__half2*)(NSt + ((size_t)((u * 2 + (m >> 6)) * 32 + (n >> 5))) * 2560
                            + (m & 63) * 40 + (n & 31)) = h;
            }
        }
    }
}

// ---------------------------------------------------------------------------
// Kernel 3: out GEMM. A fp16 (g_NSt) + B fp32 direct (Wout), inline convert.
// BM=64, BN=64, BK=64 (2 sub-tiles), 16 iters, 3-stage cp.async.
// 256 thr = 8 warps (2m x 4n), warp 32m x 16n. grid = (4 ot, 2 mt, 16 u).
// smem: A 3x10240 | F32 3x17408 | F16 2x9216 = 101376 B
// ---------------------------------------------------------------------------
#define OA_OFF   0
#define OF32_OFF 30720
#define OF16_OFF 82944
#define OT_SMEM  101376

__global__ __launch_bounds__(256) void out_kernel(
    const float* __restrict__ Wout,
    float* __restrict__ out)
{
    extern __shared__ __align__(16) char smem[];
    const int t = threadIdx.x;
    const int lane = t & 31;
    const int w = t >> 5;
    const int mw = (w & 1) * 32;
    const int nw = (w >> 1) * 16;
    const int u = blockIdx.z;
    const int mt_b = blockIdx.y;
    const int ot = blockIdx.x;
    const int m0 = mt_b * 64;
    const int n0 = ot * 64;

    const char* gA = (const char*)((const __half*)g_NSt + (size_t)((u * 2 + mt_b) * 32) * 2560);

    auto ISSUE = [&](int it) {
        int s = it % 3;
        char* Asm = smem + OA_OFF + s * 10240;
        const char* gAsrc = gA + (size_t)it * 10240;
        #pragma unroll
        for (int i = 0; i < 3; i++) {
            int q = t + i * 256;
            if (q < 640) CPA16(sptr(Asm + q * 16), gAsrc + q * 16);
        }
        // B fp32: 64 k-rows x 256B, row stride 272B
        char* Bf = smem + OF32_OFF + s * 17408;
        const float* bbase = Wout + ((size_t)u * Nn + it * 64) * Oo + n0;
        #pragma unroll
        for (int i = 0; i < 4; i++) {
            int q = t + i * 256;
            int r = q >> 4, c16 = q & 15;
            CPA16(sptr(Bf + r * 272 + c16 * 16), (const char*)(bbase + (size_t)r * Oo + c16 * 4));
        }
        CPCOMMIT();
    };

    auto CONVERT = [&](int it) {
        const char* Bf = smem + OF32_OFF + (it % 3) * 17408;
        __half* Bh = (__half*)(smem + OF16_OFF + (it & 1) * 9216);
        #pragma unroll
        for (int i = 0; i < 4; i++) {
            int q = t + i * 256;
            int r = q >> 4, c16 = q & 15;
            float4 v = *(const float4*)(Bf + r * 272 + c16 * 16);
            uint2 p = make_uint2(h2pack(v.x, v.y), h2pack(v.z, v.w));
            *(uint2*)(Bh + r * 72 + c16 * 4) = p;
        }
    };

    float acc[2][2][4];
    #pragma unroll
    for (int i = 0; i < 2; i++)
        #pragma unroll
        for (int j = 0; j < 2; j++)
            #pragma unroll
            for (int c = 0; c < 4; c++) acc[i][j][c] = 0.f;

    ISSUE(0); ISSUE(1);

    for (int it = 0; it < 16; it++) {
        if (it + 1 < 16) { CPWAIT1(); } else { CPWAIT0(); }
        __syncthreads();
        CONVERT(it);
        __syncthreads();
        if (it + 2 < 16) ISSUE(it + 2);

        #pragma unroll
        for (int ktl = 0; ktl < 2; ktl++) {
            const __half* As = (const __half*)(smem + OA_OFF + (it % 3) * 10240 + ktl * 5120);
            const __half* Bs = (const __half*)(smem + OF16_OFF + (it & 1) * 9216) + ktl * 32 * 72;
            #pragma unroll
            for (int ks = 0; ks < 2; ks++) {
                const int kc = ks * 16;
                uint32_t af[2][4];
                {
                    int i = lane & 7, grp = lane >> 3;
                    int mrow = (grp & 1) * 8 + i;
                    int kcol = kc + (grp >> 1) * 8;
                    #pragma unroll
                    for (int mt = 0; mt < 2; mt++)
                        ldmA(af[mt], sptr(As + (mw + mt * 16 + mrow) * 40 + kcol));
                }
                uint32_t bf[2][2];
                {
                    int i = lane & 7, grp = lane >> 3;
                    int krow = kc + (grp & 1) * 8 + i;
                    int ncol = nw + (grp >> 1) * 8;
                    uint32_t r[4];
                    ldmBT(r, sptr(Bs + krow * 72 + ncol));
                    bf[0][0] = r[0]; bf[0][1] = r[1];
                    bf[1][0] = r[2]; bf[1][1] = r[3];
                }
                #pragma unroll
                for (int mt = 0; mt < 2; mt++)
                    #pragma unroll
                    for (int ntt = 0; ntt < 2; ntt++)
                        mma16816(acc[mt][ntt], af[mt], bf[ntt]);
            }
        }
        __syncthreads();
    }

    #pragma unroll
    for (int mt = 0; mt < 2; mt++) {
        #pragma unroll
        for (int half = 0; half < 2; half++) {
            int m = m0 + mw + mt * 16 + half * 8 + (lane >> 2);
            #pragma unroll
            for (int ntt = 0; ntt < 2; ntt++) {
                int n = n0 + nw + ntt * 8 + (lane & 3) * 2;
                float2 res = { acc[mt][ntt][half * 2 + 0], acc[mt][ntt][half * 2 + 1] };
                *(float2*)(out + ((size_t)m * Uu + u) * Oo + n) = res;
            }
        }
    }
}

// ---------------------------------------------------------------------------
// Launch. inputs: 0:X 1:state 2:W 3:Win 4:bias 5:Wout 6:sr 7:adaptive_lr 8:temp
// ---------------------------------------------------------------------------
extern "C" void kernel_launch(void* const* d_in, const int* in_sizes, int n_in,
                              void* d_out, int out_size) {
    const float* X     = (const float*)d_in[0];
    const float* state = (const float*)d_in[1];
    const float* W     = (const float*)d_in[2];
    const float* Win   = (const float*)d_in[3];
    const float* bias  = (const float*)d_in[4];
    const float* Wout  = (const float*)d_in[5];
    const float* sr    = (const float*)d_in[6];
    const float* alr   = (const float*)d_in[7];
    const float* temp  = (const float*)d_in[8];

    float* out_state = (float*)d_out;
    float* out_out   = out_state + (size_t)Bb * Uu * Nn;

    cudaFuncSetAttribute(state_kernel, cudaFuncAttributeMaxDynamicSharedMemorySize, ST_SMEM);
    cudaFuncSetAttribute(out_kernel,   cudaFuncAttributeMaxDynamicSharedMemorySize, OT_SMEM);

    prep_kernel<<<384, 256>>>(X, state, sr, alr, temp);
    state_kernel<<<dim3(16, Uu), 256, ST_SMEM>>>(state, bias, W, Win, out_state);
    out_kernel<<<dim3(4, 2, Uu), 256, OT_SMEM>>>(Wout, out_out);
}

// round 16
// speedup vs baseline: 1.0309x; 1.0309x over previous
#include <cuda_runtime.h>
#include <cuda_fp16.h>
#include <math.h>
#include <stdint.h>

#define Bb 128
#define Uu 16
#define Dd 256
#define Nn 1024
#define Oo 256

__device__ float g_lr[Bb * Uu];

// fp16 tile images
// g_At [u][40kt][128m x 40h]      : state-GEMM A tiles (X | sr*state)
// g_NSt[u][2mt][32kt][64m x 40h]  : out-GEMM A tiles (fp16 new_state)
__device__ uint4 g_At[409600];
__device__ uint4 g_NSt[327680];

// ---------------------------------------------------------------------------
// helpers
// ---------------------------------------------------------------------------
__device__ __forceinline__ uint32_t sptr(const void* p) {
    return (uint32_t)__cvta_generic_to_shared(p);
}
__device__ __forceinline__ void ldmA(uint32_t* r, uint32_t addr) {
    asm volatile("ldmatrix.sync.aligned.m8n8.x4.shared.b16 {%0,%1,%2,%3}, [%4];"
                 : "=r"(r[0]), "=r"(r[1]), "=r"(r[2]), "=r"(r[3]) : "r"(addr));
}
__device__ __forceinline__ void ldmBT(uint32_t* r, uint32_t addr) {
    asm volatile("ldmatrix.sync.aligned.m8n8.x4.trans.shared.b16 {%0,%1,%2,%3}, [%4];"
                 : "=r"(r[0]), "=r"(r[1]), "=r"(r[2]), "=r"(r[3]) : "r"(addr));
}
__device__ __forceinline__ void mma16816(float* c, const uint32_t* a, const uint32_t* b) {
    asm volatile(
        "mma.sync.aligned.m16n8k16.row.col.f32.f16.f16.f32 "
        "{%0,%1,%2,%3},{%4,%5,%6,%7},{%8,%9},{%0,%1,%2,%3};"
        : "+f"(c[0]), "+f"(c[1]), "+f"(c[2]), "+f"(c[3])
        : "r"(a[0]), "r"(a[1]), "r"(a[2]), "r"(a[3]), "r"(b[0]), "r"(b[1]));
}
__device__ __forceinline__ uint32_t h2pack(float x, float y) {
    __half2 h = __floats2half2_rn(x, y);
    return *(uint32_t*)&h;
}
__device__ __forceinline__ uint4 pack8(float4 a, float4 b) {
    return make_uint4(h2pack(a.x, a.y), h2pack(a.z, a.w),
                      h2pack(b.x, b.y), h2pack(b.z, b.w));
}

#define CPA16(dst, src) \
    asm volatile("cp.async.cg.shared.global [%0], [%1], 16;" :: "r"(dst), "l"(src))
#define CPCOMMIT() asm volatile("cp.async.commit_group;" ::: "memory")
#define CPWAIT1()  asm volatile("cp.async.wait_group 1;" ::: "memory")
#define CPWAIT0()  asm volatile("cp.async.wait_group 0;" ::: "memory")

// ---------------------------------------------------------------------------
// Kernel 0: prep (A tiles only) + lr softmax folded in.
// grid.x = 256 convert blocks + 128 lr blocks. 256 threads.
// ---------------------------------------------------------------------------
__global__ __launch_bounds__(256) void prep_kernel(
    const float* __restrict__ X,
    const float* __restrict__ state,
    const float* __restrict__ sr,
    const float* __restrict__ alr,
    const float* __restrict__ temp)
{
    const int t = threadIdx.x;

    if (blockIdx.x >= 256) {
        // ---- lr for batch b
        __shared__ float logits[Uu];
        const int b = blockIdx.x - 256;
        const int u = t >> 4;
        const int l16 = t & 15;
        const float* xp = X + (b * Uu + u) * Dd;
        const float* ap = alr + u * Dd;
        float s = 0.f;
        #pragma unroll
        for (int d = l16; d < Dd; d += 16) s += xp[d] * ap[d];
        #pragma unroll
        for (int off = 1; off < 16; off <<= 1) s += __shfl_xor_sync(0xffffffffu, s, off);
        if (l16 == 0) logits[u] = s / temp[0];
        __syncthreads();
        if (t == 0) {
            float m = -INFINITY;
            #pragma unroll
            for (int i = 0; i < Uu; i++) m = fmaxf(m, logits[i]);
            float e[Uu], denom = 0.f;
            #pragma unroll
            for (int i = 0; i < Uu; i++) { e[i] = __expf(logits[i] - m); denom += e[i]; }
            float inv = 1.f / denom;
            #pragma unroll
            for (int i = 0; i < Uu; i++) g_lr[b * Uu + i] = e[i] * inv;
        }
        return;
    }

    const int tid = blockIdx.x * 256 + t;
    const int nth = 256 * 256;
    __half* At = (__half*)g_At;

    // A-X: u,b,k8(32) -> 65536
    for (int i = tid; i < 65536; i += nth) {
        int u = i >> 12, r = i & 4095, b = r >> 5, k8 = r & 31;
        const float4* s = (const float4*)X + ((size_t)(b * Uu + u) * 64 + k8 * 2);
        float4 v0 = s[0], v1 = s[1];
        int k = k8 * 8, kt = k >> 5;
        *(uint4*)(At + ((size_t)(u * 40 + kt)) * 5120 + b * 40 + (k & 31)) = pack8(v0, v1);
    }
    // A-state: u,b,k8(128) -> 262144 (fold sr)
    for (int i = tid; i < 262144; i += nth) {
        int u = i >> 14, r = i & 16383, b = r >> 7, k8 = r & 127;
        float srv = __ldg(sr + u);
        const float4* s = (const float4*)state + ((size_t)(b * Uu + u) * 256 + k8 * 2);
        float4 v0 = s[0], v1 = s[1];
        v0.x *= srv; v0.y *= srv; v0.z *= srv; v0.w *= srv;
        v1.x *= srv; v1.y *= srv; v1.z *= srv; v1.w *= srv;
        int k = 256 + k8 * 8, kt = k >> 5;
        *(uint4*)(At + ((size_t)(u * 40 + kt)) * 5120 + b * 40 + (k & 31)) = pack8(v0, v1);
    }
}

// ---------------------------------------------------------------------------
// Kernel 2: state GEMM. A tiles fp16 (g_At) + B fp32 direct (Win/W), inline
// convert. BM=128, BN=128, BK=32, 40 kts, 3-stage cp.async.
// 512 thr = 16 warps (4m x 4n); warp 32m x 32n. grid = (8 nt, 16 u).
// smem: A 3x10240 | F32 3x16896 | F16 2x8704 = 98816 B. 1 block/SM.
// ---------------------------------------------------------------------------
#define SA_OFF   0
#define SF32_OFF 30720
#define SF16_OFF 81408
#define ST_SMEM  98816

__global__ __launch_bounds__(512) void state_kernel(
    const float* __restrict__ state,
    const float* __restrict__ bias,
    const float* __restrict__ W,
    const float* __restrict__ Win,
    float* __restrict__ out_state)
{
    extern __shared__ __align__(16) char smem[];
    const int t = threadIdx.x;
    const int lane = t & 31;
    const int w = t >> 5;
    const int mw = (w & 3) * 32;       // warp m-offset (4 groups)
    const int nw = (w >> 2) * 32;      // warp n-offset (4 groups)
    const int u = blockIdx.y;
    const int nt = blockIdx.x;
    const int n0 = nt * 128;

    const __half* gA = (const __half*)g_At + (size_t)(u * 40) * 5120;

    auto ISSUE = [&](int kt) {
        int s = kt % 3;
        // A fp16 tile: 640 x 16B
        char* Asm = smem + SA_OFF + s * 10240;
        const char* gAsrc = (const char*)(gA + (size_t)kt * 5120);
        #pragma unroll
        for (int i = 0; i < 2; i++) {
            int q = t + i * 512;
            if (q < 640) CPA16(sptr(Asm + q * 16), gAsrc + q * 16);
        }
        // B fp32 tile: 32 k-rows x 512B = 1024 x 16B, row stride 528B
        char* Bf = smem + SF32_OFF + s * 16896;
        int kg0 = kt * 32;
        const float* bbase = (kg0 < Dd)
            ? (Win + ((size_t)u * Dd + kg0) * Nn + n0)
            : (W + ((size_t)u * Nn + (kg0 - Dd)) * Nn + n0);
        #pragma unroll
        for (int i = 0; i < 2; i++) {
            int q = t + i * 512;
            int r = q >> 5, c16 = q & 31;
            CPA16(sptr(Bf + r * 528 + c16 * 16), (const char*)(bbase + (size_t)r * Nn + c16 * 4));
        }
        CPCOMMIT();
    };

    auto CONVERT = [&](int kt) {
        const char* Bf = smem + SF32_OFF + (kt % 3) * 16896;
        __half* Bh = (__half*)(smem + SF16_OFF + (kt & 1) * 8704);
        #pragma unroll
        for (int i = 0; i < 2; i++) {
            int q = t + i * 512;
            int r = q >> 5, c16 = q & 31;
            float4 v = *(const float4*)(Bf + r * 528 + c16 * 16);
            uint2 p = make_uint2(h2pack(v.x, v.y), h2pack(v.z, v.w));
            *(uint2*)(Bh + r * 136 + c16 * 4) = p;
        }
    };

    float acc[2][4][4];
    #pragma unroll
    for (int i = 0; i < 2; i++)
        #pragma unroll
        for (int j = 0; j < 4; j++)
            #pragma unroll
            for (int c = 0; c < 4; c++) acc[i][j][c] = 0.f;

    ISSUE(0); ISSUE(1);

    for (int kt = 0; kt < 40; kt++) {
        // wait_group 1 does not guarantee group kt complete when it is the
        // only outstanding group (tail) — drain fully there.
        if (kt + 1 < 40) { CPWAIT1(); } else { CPWAIT0(); }
        __syncthreads();
        CONVERT(kt);
        __syncthreads();
        if (kt + 2 < 40) ISSUE(kt + 2);

        const __half* As = (const __half*)(smem + SA_OFF + (kt % 3) * 10240);
        const __half* Bs = (const __half*)(smem + SF16_OFF + (kt & 1) * 8704);
        #pragma unroll
        for (int ks = 0; ks < 2; ks++) {
            const int kc = ks * 16;
            uint32_t af[2][4];
            {
                int i = lane & 7, grp = lane >> 3;
                int mrow = (grp & 1) * 8 + i;
                int kcol = kc + (grp >> 1) * 8;
                #pragma unroll
                for (int mt = 0; mt < 2; mt++)
                    ldmA(af[mt], sptr(As + (mw + mt * 16 + mrow) * 40 + kcol));
            }
            uint32_t bf[4][2];
            {
                int i = lane & 7, grp = lane >> 3;
                #pragma unroll
                for (int pair = 0; pair < 2; pair++) {
                    int krow = kc + (grp & 1) * 8 + i;
                    int ncol = nw + pair * 16 + (grp >> 1) * 8;
                    uint32_t r[4];
                    ldmBT(r, sptr(Bs + krow * 136 + ncol));
                    bf[pair * 2 + 0][0] = r[0]; bf[pair * 2 + 0][1] = r[1];
                    bf[pair * 2 + 1][0] = r[2]; bf[pair * 2 + 1][1] = r[3];
                }
            }
            #pragma unroll
            for (int mt = 0; mt < 2; mt++)
                #pragma unroll
                for (int ntt = 0; ntt < 4; ntt++)
                    mma16816(acc[mt][ntt], af[mt], bf[ntt]);
        }
    }

    // epilogue: bias + tanh + leaky mix; also write fp16 tile image for out GEMM
    __half* NSt = (__half*)g_NSt;
    #pragma unroll
    for (int mt = 0; mt < 2; mt++) {
        #pragma unroll
        for (int half = 0; half < 2; half++) {
            int m = mw + mt * 16 + half * 8 + (lane >> 2);
            float lrv = g_lr[m * Uu + u];
            #pragma unroll
            for (int ntt = 0; ntt < 4; ntt++) {
                int n = n0 + nw + ntt * 8 + (lane & 3) * 2;
                float c0 = acc[mt][ntt][half * 2 + 0];
                float c1 = acc[mt][ntt][half * 2 + 1];
                size_t ro = ((size_t)m * Uu + u) * Nn + n;
                float2 so = *(const float2*)(state + ro);
                float2 bi = *(const float2*)(bias + (size_t)u * Nn + n);
                float2 res;
                res.x = so.x + lrv * (tanhf(c0 + bi.x) - so.x);
                res.y = so.y + lrv * (tanhf(c1 + bi.y) - so.y);
                *(float2*)(out_state + ro) = res;
                __half2 h = __floats2half2_rn(res.x, res.y);
                *(__half2*)(NSt + ((size_t)((u * 2 + (m >> 6)) * 32 + (n >> 5))) * 2560
                            + (m & 63) * 40 + (n & 31)) = h;
            }
        }
    }
}

// ---------------------------------------------------------------------------
// Kernel 3: out GEMM. A fp16 (g_NSt) + B fp32 direct (Wout), inline convert.
// BM=64, BN=64, BK=64 (2 sub-tiles), 16 iters, 3-stage cp.async.
// 256 thr = 8 warps (2m x 4n), warp 32m x 16n. grid = (4 ot, 2 mt, 16 u).
// smem: A 3x10240 | F32 3x17408 | F16 2x9216 = 101376 B
// ---------------------------------------------------------------------------
#define OA_OFF   0
#define OF32_OFF 30720
#define OF16_OFF 82944
#define OT_SMEM  101376

__global__ __launch_bounds__(256) void out_kernel(
    const float* __restrict__ Wout,
    float* __restrict__ out)
{
    extern __shared__ __align__(16) char smem[];
    const int t = threadIdx.x;
    const int lane = t & 31;
    const int w = t >> 5;
    const int mw = (w & 1) * 32;
    const int nw = (w >> 1) * 16;
    const int u = blockIdx.z;
    const int mt_b = blockIdx.y;
    const int ot = blockIdx.x;
    const int m0 = mt_b * 64;
    const int n0 = ot * 64;

    const char* gA = (const char*)((const __half*)g_NSt + (size_t)((u * 2 + mt_b) * 32) * 2560);

    auto ISSUE = [&](int it) {
        int s = it % 3;
        char* Asm = smem + OA_OFF + s * 10240;
        const char* gAsrc = gA + (size_t)it * 10240;
        #pragma unroll
        for (int i = 0; i < 3; i++) {
            int q = t + i * 256;
            if (q < 640) CPA16(sptr(Asm + q * 16), gAsrc + q * 16);
        }
        // B fp32: 64 k-rows x 256B, row stride 272B
        char* Bf = smem + OF32_OFF + s * 17408;
        const float* bbase = Wout + ((size_t)u * Nn + it * 64) * Oo + n0;
        #pragma unroll
        for (int i = 0; i < 4; i++) {
            int q = t + i * 256;
            int r = q >> 4, c16 = q & 15;
            CPA16(sptr(Bf + r * 272 + c16 * 16), (const char*)(bbase + (size_t)r * Oo + c16 * 4));
        }
        CPCOMMIT();
    };

    auto CONVERT = [&](int it) {
        const char* Bf = smem + OF32_OFF + (it % 3) * 17408;
        __half* Bh = (__half*)(smem + OF16_OFF + (it & 1) * 9216);
        #pragma unroll
        for (int i = 0; i < 4; i++) {
            int q = t + i * 256;
            int r = q >> 4, c16 = q & 15;
            float4 v = *(const float4*)(Bf + r * 272 + c16 * 16);
            uint2 p = make_uint2(h2pack(v.x, v.y), h2pack(v.z, v.w));
            *(uint2*)(Bh + r * 72 + c16 * 4) = p;
        }
    };

    float acc[2][2][4];
    #pragma unroll
    for (int i = 0; i < 2; i++)
        #pragma unroll
        for (int j = 0; j < 2; j++)
            #pragma unroll
            for (int c = 0; c < 4; c++) acc[i][j][c] = 0.f;

    ISSUE(0); ISSUE(1);

    for (int it = 0; it < 16; it++) {
        if (it + 1 < 16) { CPWAIT1(); } else { CPWAIT0(); }
        __syncthreads();
        CONVERT(it);
        __syncthreads();
        if (it + 2 < 16) ISSUE(it + 2);

        #pragma unroll
        for (int ktl = 0; ktl < 2; ktl++) {
            const __half* As = (const __half*)(smem + OA_OFF + (it % 3) * 10240 + ktl * 5120);
            const __half* Bs = (const __half*)(smem + OF16_OFF + (it & 1) * 9216) + ktl * 32 * 72;
            #pragma unroll
            for (int ks = 0; ks < 2; ks++) {
                const int kc = ks * 16;
                uint32_t af[2][4];
                {
                    int i = lane & 7, grp = lane >> 3;
                    int mrow = (grp & 1) * 8 + i;
                    int kcol = kc + (grp >> 1) * 8;
                    #pragma unroll
                    for (int mt = 0; mt < 2; mt++)
                        ldmA(af[mt], sptr(As + (mw + mt * 16 + mrow) * 40 + kcol));
                }
                uint32_t bf[2][2];
                {
                    int i = lane & 7, grp = lane >> 3;
                    int krow = kc + (grp & 1) * 8 + i;
                    int ncol = nw + (grp >> 1) * 8;
                    uint32_t r[4];
                    ldmBT(r, sptr(Bs + krow * 72 + ncol));
                    bf[0][0] = r[0]; bf[0][1] = r[1];
                    bf[1][0] = r[2]; bf[1][1] = r[3];
                }
                #pragma unroll
                for (int mt = 0; mt < 2; mt++)
                    #pragma unroll
                    for (int ntt = 0; ntt < 2; ntt++)
                        mma16816(acc[mt][ntt], af[mt], bf[ntt]);
            }
        }
        __syncthreads();
    }

    #pragma unroll
    for (int mt = 0; mt < 2; mt++) {
        #pragma unroll
        for (int half = 0; half < 2; half++) {
            int m = m0 + mw + mt * 16 + half * 8 + (lane >> 2);
            #pragma unroll
            for (int ntt = 0; ntt < 2; ntt++) {
                int n = n0 + nw + ntt * 8 + (lane & 3) * 2;
                float2 res = { acc[mt][ntt][half * 2 + 0], acc[mt][ntt][half * 2 + 1] };
                *(float2*)(out + ((size_t)m * Uu + u) * Oo + n) = res;
            }
        }
    }
}

// ---------------------------------------------------------------------------
// Launch. inputs: 0:X 1:state 2:W 3:Win 4:bias 5:Wout 6:sr 7:adaptive_lr 8:temp
// ---------------------------------------------------------------------------
extern "C" void kernel_launch(void* const* d_in, const int* in_sizes, int n_in,
                              void* d_out, int out_size) {
    const float* X     = (const float*)d_in[0];
    const float* state = (const float*)d_in[1];
    const float* W     = (const float*)d_in[2];
    const float* Win   = (const float*)d_in[3];
    const float* bias  = (const float*)d_in[4];
    const float* Wout  = (const float*)d_in[5];
    const float* sr    = (const float*)d_in[6];
    const float* alr   = (const float*)d_in[7];
    const float* temp  = (const float*)d_in[8];

    float* out_state = (float*)d_out;
    float* out_out   = out_state + (size_t)Bb * Uu * Nn;

    cudaFuncSetAttribute(state_kernel, cudaFuncAttributeMaxDynamicSharedMemorySize, ST_SMEM);
    cudaFuncSetAttribute(out_kernel,   cudaFuncAttributeMaxDynamicSharedMemorySize, OT_SMEM);

    prep_kernel<<<384, 256>>>(X, state, sr, alr, temp);
    state_kernel<<<dim3(8, Uu), 512, ST_SMEM>>>(state, bias, W, Win, out_state);
    out_kernel<<<dim3(4, 2, Uu), 256, OT_SMEM>>>(Wout, out_out);
}

// round 17
// speedup vs baseline: 1.1071x; 1.0740x over previous
#include <cuda_runtime.h>
#include <cuda_fp16.h>
#include <math.h>
#include <stdint.h>

#define Bb 128
#define Uu 16
#define Dd 256
#define Nn 1024
#define Oo 256

__device__ float g_lr[Bb * Uu];

// fp16 tile images
// g_At [u][40kt][128m x 40h]      : state-GEMM A tiles (X | sr*state)
// g_NSt[u][2mt][32kt][64m x 40h]  : out-GEMM A tiles (fp16 new_state)
__device__ uint4 g_At[409600];
__device__ uint4 g_NSt[327680];

// ---------------------------------------------------------------------------
// helpers
// ---------------------------------------------------------------------------
__device__ __forceinline__ uint32_t sptr(const void* p) {
    return (uint32_t)__cvta_generic_to_shared(p);
}
__device__ __forceinline__ void ldmA(uint32_t* r, uint32_t addr) {
    asm volatile("ldmatrix.sync.aligned.m8n8.x4.shared.b16 {%0,%1,%2,%3}, [%4];"
                 : "=r"(r[0]), "=r"(r[1]), "=r"(r[2]), "=r"(r[3]) : "r"(addr));
}
__device__ __forceinline__ void ldmBT(uint32_t* r, uint32_t addr) {
    asm volatile("ldmatrix.sync.aligned.m8n8.x4.trans.shared.b16 {%0,%1,%2,%3}, [%4];"
                 : "=r"(r[0]), "=r"(r[1]), "=r"(r[2]), "=r"(r[3]) : "r"(addr));
}
__device__ __forceinline__ void mma16816(float* c, const uint32_t* a, const uint32_t* b) {
    asm volatile(
        "mma.sync.aligned.m16n8k16.row.col.f32.f16.f16.f32 "
        "{%0,%1,%2,%3},{%4,%5,%6,%7},{%8,%9},{%0,%1,%2,%3};"
        : "+f"(c[0]), "+f"(c[1]), "+f"(c[2]), "+f"(c[3])
        : "r"(a[0]), "r"(a[1]), "r"(a[2]), "r"(a[3]), "r"(b[0]), "r"(b[1]));
}
__device__ __forceinline__ uint32_t h2pack(float x, float y) {
    __half2 h = __floats2half2_rn(x, y);
    return *(uint32_t*)&h;
}
__device__ __forceinline__ uint4 pack8(float4 a, float4 b) {
    return make_uint4(h2pack(a.x, a.y), h2pack(a.z, a.w),
                      h2pack(b.x, b.y), h2pack(b.z, b.w));
}

#define CPA16(dst, src) \
    asm volatile("cp.async.cg.shared.global [%0], [%1], 16;" :: "r"(dst), "l"(src))
#define CPCOMMIT() asm volatile("cp.async.commit_group;" ::: "memory")
#define CPWAIT2()  asm volatile("cp.async.wait_group 2;" ::: "memory")
#define CPWAIT1()  asm volatile("cp.async.wait_group 1;" ::: "memory")
#define CPWAIT0()  asm volatile("cp.async.wait_group 0;" ::: "memory")

// ---------------------------------------------------------------------------
// Kernel 0: prep (A tiles only) + lr softmax folded in.
// grid.x = 768 convert blocks + 128 lr blocks. 256 threads.
// ---------------------------------------------------------------------------
__global__ __launch_bounds__(256) void prep_kernel(
    const float* __restrict__ X,
    const float* __restrict__ state,
    const float* __restrict__ sr,
    const float* __restrict__ alr,
    const float* __restrict__ temp)
{
    const int t = threadIdx.x;

    if (blockIdx.x >= 768) {
        // ---- lr for batch b
        __shared__ float logits[Uu];
        const int b = blockIdx.x - 768;
        const int u = t >> 4;
        const int l16 = t & 15;
        const float* xp = X + (b * Uu + u) * Dd;
        const float* ap = alr + u * Dd;
        float s = 0.f;
        #pragma unroll
        for (int d = l16; d < Dd; d += 16) s += xp[d] * ap[d];
        #pragma unroll
        for (int off = 1; off < 16; off <<= 1) s += __shfl_xor_sync(0xffffffffu, s, off);
        if (l16 == 0) logits[u] = s / temp[0];
        __syncthreads();
        if (t == 0) {
            float m = -INFINITY;
            #pragma unroll
            for (int i = 0; i < Uu; i++) m = fmaxf(m, logits[i]);
            float e[Uu], denom = 0.f;
            #pragma unroll
            for (int i = 0; i < Uu; i++) { e[i] = __expf(logits[i] - m); denom += e[i]; }
            float inv = 1.f / denom;
            #pragma unroll
            for (int i = 0; i < Uu; i++) g_lr[b * Uu + i] = e[i] * inv;
        }
        return;
    }

    const int tid = blockIdx.x * 256 + t;
    const int nth = 768 * 256;
    __half* At = (__half*)g_At;

    // A-X: u,b,k8(32) -> 65536
    for (int i = tid; i < 65536; i += nth) {
        int u = i >> 12, r = i & 4095, b = r >> 5, k8 = r & 31;
        const float4* s = (const float4*)X + ((size_t)(b * Uu + u) * 64 + k8 * 2);
        float4 v0 = s[0], v1 = s[1];
        int k = k8 * 8, kt = k >> 5;
        *(uint4*)(At + ((size_t)(u * 40 + kt)) * 5120 + b * 40 + (k & 31)) = pack8(v0, v1);
    }
    // A-state: u,b,k8(128) -> 262144 (fold sr)
    for (int i = tid; i < 262144; i += nth) {
        int u = i >> 14, r = i & 16383, b = r >> 7, k8 = r & 127;
        float srv = __ldg(sr + u);
        const float4* s = (const float4*)state + ((size_t)(b * Uu + u) * 256 + k8 * 2);
        float4 v0 = s[0], v1 = s[1];
        v0.x *= srv; v0.y *= srv; v0.z *= srv; v0.w *= srv;
        v1.x *= srv; v1.y *= srv; v1.z *= srv; v1.w *= srv;
        int k = 256 + k8 * 8, kt = k >> 5;
        *(uint4*)(At + ((size_t)(u * 40 + kt)) * 5120 + b * 40 + (k & 31)) = pack8(v0, v1);
    }
}

// ---------------------------------------------------------------------------
// Kernel 2: state GEMM. A fp16 tiles + B fp32 direct (Win/W), pipelined
// convert (tile kt+1 converted while MMA consumes kt). BM=128, BN=128,
// BK=32, 40 kts, 4-stage cp.async, ONE sync per iteration.
// 512 thr = 16 warps (4m x 4n); warp 32m x 32n. grid = (8 nt, 16 u).
// smem: A 4x10240 | F32 4x16896 | F16 2x8704 = 125952 B. 1 block/SM.
// ---------------------------------------------------------------------------
#define SA_OFF   0
#define SF32_OFF 40960
#define SF16_OFF 108544
#define ST_SMEM  125952

__global__ __launch_bounds__(512) void state_kernel(
    const float* __restrict__ state,
    const float* __restrict__ bias,
    const float* __restrict__ W,
    const float* __restrict__ Win,
    float* __restrict__ out_state)
{
    extern __shared__ __align__(16) char smem[];
    const int t = threadIdx.x;
    const int lane = t & 31;
    const int w = t >> 5;
    const int mw = (w & 3) * 32;
    const int nw = (w >> 2) * 32;
    const int u = blockIdx.y;
    const int nt = blockIdx.x;
    const int n0 = nt * 128;

    const __half* gA = (const __half*)g_At + (size_t)(u * 40) * 5120;

    auto ISSUE = [&](int kt) {
        int s = kt & 3;
        char* Asm = smem + SA_OFF + s * 10240;
        const char* gAsrc = (const char*)(gA + (size_t)kt * 5120);
        #pragma unroll
        for (int i = 0; i < 2; i++) {
            int q = t + i * 512;
            if (q < 640) CPA16(sptr(Asm + q * 16), gAsrc + q * 16);
        }
        char* Bf = smem + SF32_OFF + s * 16896;
        int kg0 = kt * 32;
        const float* bbase = (kg0 < Dd)
            ? (Win + ((size_t)u * Dd + kg0) * Nn + n0)
            : (W + ((size_t)u * Nn + (kg0 - Dd)) * Nn + n0);
        #pragma unroll
        for (int i = 0; i < 2; i++) {
            int q = t + i * 512;
            int r = q >> 5, c16 = q & 31;
            CPA16(sptr(Bf + r * 528 + c16 * 16), (const char*)(bbase + (size_t)r * Nn + c16 * 4));
        }
        CPCOMMIT();
    };

    auto CONVERT = [&](int kt) {
        const char* Bf = smem + SF32_OFF + (kt & 3) * 16896;
        __half* Bh = (__half*)(smem + SF16_OFF + (kt & 1) * 8704);
        #pragma unroll
        for (int i = 0; i < 2; i++) {
            int q = t + i * 512;
            int r = q >> 5, c16 = q & 31;
            float4 v = *(const float4*)(Bf + r * 528 + c16 * 16);
            uint2 p = make_uint2(h2pack(v.x, v.y), h2pack(v.z, v.w));
            *(uint2*)(Bh + r * 136 + c16 * 4) = p;
        }
    };

    float acc[2][4][4];
    #pragma unroll
    for (int i = 0; i < 2; i++)
        #pragma unroll
        for (int j = 0; j < 4; j++)
            #pragma unroll
            for (int c = 0; c < 4; c++) acc[i][j][c] = 0.f;

    // prologue: 3 groups in flight; convert tile 0
    ISSUE(0); ISSUE(1); ISSUE(2);
    CPWAIT2();            // group 0 complete
    __syncthreads();
    CONVERT(0);

    for (int kt = 0; kt < 40; kt++) {
        // guarantee group kt+1 complete (for convert) and kt (for MMA A):
        // newest outstanding is kt+2 while issues continue; at kt==38 the
        // newest IS kt+1 -> full drain (wait_group-1 tail hazard).
        if (kt < 38) { CPWAIT1(); } else if (kt == 38) { CPWAIT0(); }
        __syncthreads();
        if (kt + 1 < 40) CONVERT(kt + 1);
        if (kt + 3 < 40) ISSUE(kt + 3);

        const __half* As = (const __half*)(smem + SA_OFF + (kt & 3) * 10240);
        const __half* Bs = (const __half*)(smem + SF16_OFF + (kt & 1) * 8704);
        #pragma unroll
        for (int ks = 0; ks < 2; ks++) {
            const int kc = ks * 16;
            uint32_t af[2][4];
            {
                int i = lane & 7, grp = lane >> 3;
                int mrow = (grp & 1) * 8 + i;
                int kcol = kc + (grp >> 1) * 8;
                #pragma unroll
                for (int mt = 0; mt < 2; mt++)
                    ldmA(af[mt], sptr(As + (mw + mt * 16 + mrow) * 40 + kcol));
            }
            uint32_t bf[4][2];
            {
                int i = lane & 7, grp = lane >> 3;
                #pragma unroll
                for (int pair = 0; pair < 2; pair++) {
                    int krow = kc + (grp & 1) * 8 + i;
                    int ncol = nw + pair * 16 + (grp >> 1) * 8;
                    uint32_t r[4];
                    ldmBT(r, sptr(Bs + krow * 136 + ncol));
                    bf[pair * 2 + 0][0] = r[0]; bf[pair * 2 + 0][1] = r[1];
                    bf[pair * 2 + 1][0] = r[2]; bf[pair * 2 + 1][1] = r[3];
                }
            }
            #pragma unroll
            for (int mt = 0; mt < 2; mt++)
                #pragma unroll
                for (int ntt = 0; ntt < 4; ntt++)
                    mma16816(acc[mt][ntt], af[mt], bf[ntt]);
        }
    }

    // epilogue: bias + tanh + leaky mix; also write fp16 tile image for out GEMM
    __half* NSt = (__half*)g_NSt;
    #pragma unroll
    for (int mt = 0; mt < 2; mt++) {
        #pragma unroll
        for (int half = 0; half < 2; half++) {
            int m = mw + mt * 16 + half * 8 + (lane >> 2);
            float lrv = g_lr[m * Uu + u];
            #pragma unroll
            for (int ntt = 0; ntt < 4; ntt++) {
                int n = n0 + nw + ntt * 8 + (lane & 3) * 2;
                float c0 = acc[mt][ntt][half * 2 + 0];
                float c1 = acc[mt][ntt][half * 2 + 1];
                size_t ro = ((size_t)m * Uu + u) * Nn + n;
                float2 so = *(const float2*)(state + ro);
                float2 bi = *(const float2*)(bias + (size_t)u * Nn + n);
                float2 res;
                res.x = so.x + lrv * (tanhf(c0 + bi.x) - so.x);
                res.y = so.y + lrv * (tanhf(c1 + bi.y) - so.y);
                *(float2*)(out_state + ro) = res;
                __half2 h = __floats2half2_rn(res.x, res.y);
                *(__half2*)(NSt + ((size_t)((u * 2 + (m >> 6)) * 32 + (n >> 5))) * 2560
                            + (m & 63) * 40 + (n & 31)) = h;
            }
        }
    }
}

// ---------------------------------------------------------------------------
// Kernel 3: out GEMM. A fp16 (g_NSt) + B fp32 direct (Wout), pipelined
// convert, BK=64 (2 sub-tiles), 16 iters, 4-stage cp.async, one sync/iter.
// 256 thr = 8 warps (2m x 4n), warp 32m x 16n. grid = (4 ot, 2 mt, 16 u).
// smem: A 4x10240 | F32 4x17408 | F16 2x9216 = 129024 B
// ---------------------------------------------------------------------------
#define OA_OFF   0
#define OF32_OFF 40960
#define OF16_OFF 110592
#define OT_SMEM  129024

__global__ __launch_bounds__(256) void out_kernel(
    const float* __restrict__ Wout,
    float* __restrict__ out)
{
    extern __shared__ __align__(16) char smem[];
    const int t = threadIdx.x;
    const int lane = t & 31;
    const int w = t >> 5;
    const int mw = (w & 1) * 32;
    const int nw = (w >> 1) * 16;
    const int u = blockIdx.z;
    const int mt_b = blockIdx.y;
    const int ot = blockIdx.x;
    const int m0 = mt_b * 64;
    const int n0 = ot * 64;

    const char* gA = (const char*)((const __half*)g_NSt + (size_t)((u * 2 + mt_b) * 32) * 2560);

    auto ISSUE = [&](int it) {
        int s = it & 3;
        char* Asm = smem + OA_OFF + s * 10240;
        const char* gAsrc = gA + (size_t)it * 10240;
        #pragma unroll
        for (int i = 0; i < 3; i++) {
            int q = t + i * 256;
            if (q < 640) CPA16(sptr(Asm + q * 16), gAsrc + q * 16);
        }
        char* Bf = smem + OF32_OFF + s * 17408;
        const float* bbase = Wout + ((size_t)u * Nn + it * 64) * Oo + n0;
        #pragma unroll
        for (int i = 0; i < 4; i++) {
            int q = t + i * 256;
            int r = q >> 4, c16 = q & 15;
            CPA16(sptr(Bf + r * 272 + c16 * 16), (const char*)(bbase + (size_t)r * Oo + c16 * 4));
        }
        CPCOMMIT();
    };

    auto CONVERT = [&](int it) {
        const char* Bf = smem + OF32_OFF + (it & 3) * 17408;
        __half* Bh = (__half*)(smem + OF16_OFF + (it & 1) * 9216);
        #pragma unroll
        for (int i = 0; i < 4; i++) {
            int q = t + i * 256;
            int r = q >> 4, c16 = q & 15;
            float4 v = *(const float4*)(Bf + r * 272 + c16 * 16);
            uint2 p = make_uint2(h2pack(v.x, v.y), h2pack(v.z, v.w));
            *(uint2*)(Bh + r * 72 + c16 * 4) = p;
        }
    };

    float acc[2][2][4];
    #pragma unroll
    for (int i = 0; i < 2; i++)
        #pragma unroll
        for (int j = 0; j < 2; j++)
            #pragma unroll
            for (int c = 0; c < 4; c++) acc[i][j][c] = 0.f;

    ISSUE(0); ISSUE(1); ISSUE(2);
    CPWAIT2();
    __syncthreads();
    CONVERT(0);

    for (int it = 0; it < 16; it++) {
        if (it < 14) { CPWAIT1(); } else if (it == 14) { CPWAIT0(); }
        __syncthreads();
        if (it + 1 < 16) CONVERT(it + 1);
        if (it + 3 < 16) ISSUE(it + 3);

        #pragma unroll
        for (int ktl = 0; ktl < 2; ktl++) {
            const __half* As = (const __half*)(smem + OA_OFF + (it & 3) * 10240 + ktl * 5120);
            const __half* Bs = (const __half*)(smem + OF16_OFF + (it & 1) * 9216) + ktl * 32 * 72;
            #pragma unroll
            for (int ks = 0; ks < 2; ks++) {
                const int kc = ks * 16;
                uint32_t af[2][4];
                {
                    int i = lane & 7, grp = lane >> 3;
                    int mrow = (grp & 1) * 8 + i;
                    int kcol = kc + (grp >> 1) * 8;
                    #pragma unroll
                    for (int mt = 0; mt < 2; mt++)
                        ldmA(af[mt], sptr(As + (mw + mt * 16 + mrow) * 40 + kcol));
                }
                uint32_t bf[2][2];
                {
                    int i = lane & 7, grp = lane >> 3;
                    int krow = kc + (grp & 1) * 8 + i;
                    int ncol = nw + (grp >> 1) * 8;
                    uint32_t r[4];
                    ldmBT(r, sptr(Bs + krow * 72 + ncol));
                    bf[0][0] = r[0]; bf[0][1] = r[1];
                    bf[1][0] = r[2]; bf[1][1] = r[3];
                }
                #pragma unroll
                for (int mt = 0; mt < 2; mt++)
                    #pragma unroll
                    for (int ntt = 0; ntt < 2; ntt++)
                        mma16816(acc[mt][ntt], af[mt], bf[ntt]);
            }
        }
    }

    #pragma unroll
    for (int mt = 0; mt < 2; mt++) {
        #pragma unroll
        for (int half = 0; half < 2; half++) {
            int m = m0 + mw + mt * 16 + half * 8 + (lane >> 2);
            #pragma unroll
            for (int ntt = 0; ntt < 2; ntt++) {
                int n = n0 + nw + ntt * 8 + (lane & 3) * 2;
                float2 res = { acc[mt][ntt][half * 2 + 0], acc[mt][ntt][half * 2 + 1] };
                *(float2*)(out + ((size_t)m * Uu + u) * Oo + n) = res;
            }
        }
    }
}

// ---------------------------------------------------------------------------
// Launch. inputs: 0:X 1:state 2:W 3:Win 4:bias 5:Wout 6:sr 7:adaptive_lr 8:temp
// ---------------------------------------------------------------------------
extern "C" void kernel_launch(void* const* d_in, const int* in_sizes, int n_in,
                              void* d_out, int out_size) {
    const float* X     = (const float*)d_in[0];
    const float* state = (const float*)d_in[1];
    const float* W     = (const float*)d_in[2];
    const float* Win   = (const float*)d_in[3];
    const float* bias  = (const float*)d_in[4];
    const float* Wout  = (const float*)d_in[5];
    const float* sr    = (const float*)d_in[6];
    const float* alr   = (const float*)d_in[7];
    const float* temp  = (const float*)d_in[8];

    float* out_state = (float*)d_out;
    float* out_out   = out_state + (size_t)Bb * Uu * Nn;

    cudaFuncSetAttribute(state_kernel, cudaFuncAttributeMaxDynamicSharedMemorySize, ST_SMEM);
    cudaFuncSetAttribute(out_kernel,   cudaFuncAttributeMaxDynamicSharedMemorySize, OT_SMEM);

    prep_kernel<<<896, 256>>>(X, state, sr, alr, temp);
    state_kernel<<<dim3(8, Uu), 512, ST_SMEM>>>(state, bias, W, Win, out_state);
    out_kernel<<<dim3(4, 2, Uu), 256, OT_SMEM>>>(Wout, out_out);
}